// round 4
// baseline (speedup 1.0000x reference)
#include <cuda_runtime.h>

#define FULLMASK 0xffffffffu

constexpr int NND = 20000;
constexpr int DEG = 16;
constexpr int NQ  = 17;    // ego-graph size n = DEG+1
constexpr int TT  = 16;    // templates
constexpr int MM  = 8;     // template nodes
constexpr int DD  = 64;    // feature dim
constexpr int NODES_PER_BLK = 4;
constexpr int THREADS = 256;

// Work in base-2 units scaled by 1/EPS:  b = cost * log2(e)/EPS
constexpr float SIG       = 14.4269504088896340f;   // log2(e)/0.1
constexpr float LOGP2     = -4.0874628412503390f;   // log2(1/17)
constexpr float LOGQ2     = -3.0f;                  // log2(1/8)
constexpr float SCALEBACK = 0.0693147180559945f;    // EPS*ln(2)

__device__ __forceinline__ float ex2f_(float x) {
    float y; asm("ex2.approx.ftz.f32 %0, %1;" : "=f"(y) : "f"(x)); return y;
}
__device__ __forceinline__ float lg2f_(float x) {
    float y; asm("lg2.approx.f32 %0, %1;" : "=f"(y) : "f"(x)); return y;
}
__device__ __forceinline__ float rcpf_(float x) {
    float y; asm("rcp.approx.ftz.f32 %0, %1;" : "=f"(y) : "f"(x)); return y;
}

// dynamic smem layout (floats):
//  [0, 8192)       tfT  : transposed template features [d][t*8+j]
//  [+4352)         floc : gathered ego features [4 nodes][17][64]
//  [+1152)         c2s  : template structure [16*8][9]  (stride 9: conflict-free)
//  [+128)          wcol : per-column constant 0.5*(|tf|^2 + b)
//  [+68)           rrow : per-row constant 0.5*(|x|^2 + a)
__global__ __launch_bounds__(THREADS, 2)
void ltfgw_kernel(const float* __restrict__ x,
                  const int*   __restrict__ edge_dst,
                  const float* __restrict__ tf,
                  const float* __restrict__ tm,
                  float*       __restrict__ out)
{
    extern __shared__ float sm[];
    float* tfT  = sm;                    // 8192
    float* floc = sm + 8192;             // 4352
    float* c2s  = sm + 8192 + 4352;      // 1152 (stride 9)
    float* wcol = c2s + 1152;            // 128
    float* rrow = wcol + 128;            // 68

    const int tid = threadIdx.x;
    const int node_base = blockIdx.x * NODES_PER_BLK;

    // ---- stage templates (transposed) ----
    for (int e = tid; e < TT * MM * DD; e += THREADS) {
        int d  = e & 63;
        int tj = e >> 6;                 // t*8 + j
        tfT[d * 128 + tj] = tf[e];
    }
    for (int e = tid; e < TT * MM * MM; e += THREADS)
        c2s[(e >> 3) * 9 + (e & 7)] = tm[e];

    // ---- gather ego features: row 0 = node, rows 1..16 = neighbors ----
    for (int li = tid; li < NODES_PER_BLK * NQ * (DD / 4); li += THREADS) {
        int row = li >> 4;
        int q   = li & 15;
        int nl  = row / NQ;
        int i   = row - nl * NQ;
        int node = node_base + nl;
        int g = (i == 0) ? node : edge_dst[node * DEG + (i - 1)];
        reinterpret_cast<float4*>(floc)[row * 16 + q] =
            reinterpret_cast<const float4*>(x)[g * 16 + q];
    }
    __syncthreads();

    // ---- per-column constants: w = 0.5*(|tf_tj|^2 + (1/8)*sum_k C2[t,j,k]^2) ----
    if (tid < 128) {
        float sq = 0.f;
        #pragma unroll 8
        for (int d = 0; d < DD; d++) { float v = tfT[d * 128 + tid]; sq += v * v; }
        float bb = 0.f;
        #pragma unroll
        for (int k = 0; k < MM; k++) { float c = c2s[tid * 9 + k]; bb += c * c; }
        wcol[tid] = 0.5f * (sq + 0.125f * bb);
    } else if (tid < 128 + NODES_PER_BLK * NQ) {
        // per-row constants: r = 0.5*(|x_i|^2 + a_i), a_0 = 16/17, a_i = 1/17
        int rid = tid - 128;
        float sq = 0.f;
        #pragma unroll 8
        for (int d = 0; d < DD; d++) {
            float v = floc[rid * 64 + ((d + rid) & 63)];   // rotated: bank-conflict-free
            sq += v * v;
        }
        float a = ((rid % NQ) == 0) ? (16.f / 17.f) : (1.f / 17.f);
        rrow[rid] = 0.5f * (sq + a);
    }
    __syncthreads();

    // ---- lane mapping: 4 lanes per (node,template) pair, 2 columns per lane ----
    const int w    = tid >> 5, lane = tid & 31;
    const int nl   = w >> 1;
    const int grp  = lane >> 2, cl = lane & 3;
    const int t    = (w & 1) * 8 + grp;
    const int j0   = cl * 2;
    const int col0 = t * 8 + j0;

    // ---- feature cost (dot products), register-blocked over rows ----
    float b0[NQ], b1[NQ];
    #pragma unroll
    for (int i = 0; i < NQ; i++) { b0[i] = 0.f; b1[i] = 0.f; }

    const float* fl = floc + nl * NQ * DD;
    #pragma unroll 2
    for (int d4 = 0; d4 < DD; d4 += 4) {
        float2 t0 = *reinterpret_cast<const float2*>(&tfT[(d4 + 0) * 128 + col0]);
        float2 t1 = *reinterpret_cast<const float2*>(&tfT[(d4 + 1) * 128 + col0]);
        float2 t2 = *reinterpret_cast<const float2*>(&tfT[(d4 + 2) * 128 + col0]);
        float2 t3 = *reinterpret_cast<const float2*>(&tfT[(d4 + 3) * 128 + col0]);
        #pragma unroll
        for (int i = 0; i < NQ; i++) {
            float4 f4 = *reinterpret_cast<const float4*>(&fl[i * DD + d4]);  // broadcast
            b0[i] += f4.x * t0.x + f4.y * t1.x + f4.z * t2.x + f4.w * t3.x;
            b1[i] += f4.x * t0.y + f4.y * t1.y + f4.z * t2.y + f4.w * t3.y;
        }
    }
    // b = (r_i + w_j - dot) * SIG  == 0.5*(Mcost + constC)/EPS * log2(e)
    {
        const float w0c = wcol[col0], w1c = wcol[col0 + 1];
        #pragma unroll
        for (int i = 0; i < NQ; i++) {
            float r = rrow[nl * NQ + i];
            b0[i] = (r + w0c - b0[i]) * SIG;
            b1[i] = (r + w1c - b1[i]) * SIG;
        }
    }

    // initial H from uniform plan G = 1/136:  s_k = 16/136, z_k = 1/136
    float ht0, hr0, ht1, hr1;
    {
        float cs0 = 0.f, cs1 = 0.f;
        const float* c2r0 = &c2s[col0 * 9];
        const float* c2r1 = &c2s[(col0 + 1) * 9];
        #pragma unroll
        for (int k = 0; k < MM; k++) { cs0 += c2r0[k]; cs1 += c2r1[k]; }
        ht0 = SIG * (16.f / 136.f) * cs0; hr0 = SIG * (1.f / 136.f) * cs0;
        ht1 = SIG * (16.f / 136.f) * cs1; hr1 = SIG * (1.f / 136.f) * cs1;
        b0[0] -= ht0; b1[0] -= ht1;
        #pragma unroll
        for (int i = 1; i < NQ; i++) { b0[i] -= hr0; b1[i] -= hr1; }
    }

    float F[NQ];          // log phase: f potentials; scaled phase: t_i = rcp(rowsum)
    float K0[NQ], K1[NQ]; // kernel matrix exp2(Fhat + Ghat - b)
    float G0 = 0.f, G1 = 0.f;

    // ---- outer 0: two log-domain warmup iterations (numerically safe anchor) ----
    #pragma unroll 1
    for (int it = 0; it < 2; it++) {
        #pragma unroll
        for (int i = 0; i < NQ; i++) {
            float v0l = G0 - b0[i];
            float v1l = G1 - b1[i];
            float mx = fmaxf(v0l, v1l);
            mx = fmaxf(mx, __shfl_xor_sync(FULLMASK, mx, 1));
            mx = fmaxf(mx, __shfl_xor_sync(FULLMASK, mx, 2));
            float s = ex2f_(v0l - mx) + ex2f_(v1l - mx);
            s += __shfl_xor_sync(FULLMASK, s, 1);
            s += __shfl_xor_sync(FULLMASK, s, 2);
            F[i] = LOGP2 - (lg2f_(s) + mx);
        }
        float m0 = F[0] - b0[0], m1 = F[0] - b1[0];
        #pragma unroll
        for (int i = 1; i < NQ; i++) {
            m0 = fmaxf(m0, F[i] - b0[i]);
            m1 = fmaxf(m1, F[i] - b1[i]);
        }
        float s0l = 0.f, s1l = 0.f;
        #pragma unroll
        for (int i = 0; i < NQ; i++) {
            s0l += ex2f_(F[i] - b0[i] - m0);
            s1l += ex2f_(F[i] - b1[i] - m1);
        }
        G0 = LOGQ2 - (lg2f_(s0l) + m0);
        G1 = LOGQ2 - (lg2f_(s1l) + m1);
    }

    // ---- build anchored kernel K = exp2(F + G - b); track w = exp2(-Ghat) ----
    float v0 = 1.f, v1 = 1.f;                 // v = exp2(g - Ghat); g == Ghat now
    float wv0 = ex2f_(-G0), wv1 = ex2f_(-G1); // cold-start v for future outers
    #pragma unroll
    for (int i = 0; i < NQ; i++) {
        K0[i] = ex2f_(F[i] + G0 - b0[i]);
        K1[i] = ex2f_(F[i] + G1 - b1[i]);
    }

    float fgw = 0.f;
    const float p17 = 1.f / 17.f;

    #pragma unroll 1
    for (int outer = 0; outer < 4; outer++) {
        const int nit = outer ? 10 : 8;       // outer 0 already did 2 log iters
        #pragma unroll 1
        for (int it = 0; it < nit; it++) {
            float cs0 = 0.f, cs1 = 0.f;
            #pragma unroll
            for (int i = 0; i < NQ; i++) {
                float rs = fmaf(K0[i], v0, K1[i] * v1);
                rs += __shfl_xor_sync(FULLMASK, rs, 1);
                rs += __shfl_xor_sync(FULLMASK, rs, 2);
                float ti = rcpf_(rs);         // u_i = (1/17) * ti
                F[i] = ti;
                cs0 = fmaf(K0[i], ti, cs0);
                cs1 = fmaf(K1[i], ti, cs1);
            }
            v0 = 2.125f * rcpf_(cs0);         // (17/8) * rcp
            v1 = 2.125f * rcpf_(cs1);
        }

        // ---- plan marginals z (row 0), s (rows 1..16), and sum(P*b) ----
        float vp0 = v0 * p17, vp1 = v1 * p17;
        float z0 = F[0] * K0[0] * vp0;
        float z1 = F[0] * K1[0] * vp1;
        float gb0 = z0 * b0[0], gb1 = z1 * b1[0];
        float s0 = 0.f, s1 = 0.f;
        #pragma unroll
        for (int i = 1; i < NQ; i++) {
            float a0 = F[i] * K0[i] * vp0;
            float a1 = F[i] * K1[i] * vp1;
            s0 += a0; s1 += a1;
            gb0 = fmaf(a0, b0[i], gb0);
            gb1 = fmaf(a1, b1[i], gb1);
        }

        // assemble full s[8], z[8] across the 4-lane group
        float sf[MM], zf[MM];
        const int lb = lane & ~3;
        #pragma unroll
        for (int kk = 0; kk < 4; kk++) {
            sf[2 * kk]     = __shfl_sync(FULLMASK, s0, lb + kk);
            sf[2 * kk + 1] = __shfl_sync(FULLMASK, s1, lb + kk);
            zf[2 * kk]     = __shfl_sync(FULLMASK, z0, lb + kk);
            zf[2 * kk + 1] = __shfl_sync(FULLMASK, z1, lb + kk);
        }
        // new H = (C1 G C2): row0 uses s.C2, rows>=1 use z.C2
        float ht0n = 0.f, hr0n = 0.f, ht1n = 0.f, hr1n = 0.f;
        {
            const float* c2r0 = &c2s[col0 * 9];
            const float* c2r1 = &c2s[(col0 + 1) * 9];
            #pragma unroll
            for (int k = 0; k < MM; k++) {
                float ca = c2r0[k], cb = c2r1[k];
                ht0n = fmaf(sf[k], ca, ht0n); hr0n = fmaf(zf[k], ca, hr0n);
                ht1n = fmaf(sf[k], cb, ht1n); hr1n = fmaf(zf[k], cb, hr1n);
            }
        }
        ht0n *= SIG; hr0n *= SIG; ht1n *= SIG; hr1n *= SIG;
        float dt0 = ht0n - ht0, dt1 = ht1n - ht1;
        float dr0 = hr0n - hr0, dr1 = hr1n - hr1;

        if (outer < 3) {
            // fold Δh into cost: b_new = b_old - Δh
            b0[0] -= dt0; b1[0] -= dt1;
            #pragma unroll
            for (int i = 1; i < NQ; i++) { b0[i] -= dr0; b1[i] -= dr1; }
            ht0 = ht0n; ht1 = ht1n; hr0 = hr0n; hr1 = hr1n;

            // rescale kernel to new anchors: K' = K * u_i * v_j * exp2(Δh)
            float et0 = ex2f_(dt0), et1 = ex2f_(dt1);
            float er0 = ex2f_(dr0), er1 = ex2f_(dr1);
            float m00 = vp0 * et0, m01 = vp1 * et1;   // row 0 factors
            float mr0 = vp0 * er0, mr1 = vp1 * er1;   // rows 1..16 factors
            K0[0] *= F[0] * m00; K1[0] *= F[0] * m01;
            #pragma unroll
            for (int i = 1; i < NQ; i++) {
                float ti = F[i];
                K0[i] *= ti * mr0;
                K1[i] *= ti * mr1;
            }
            // cold-start v for next outer: exp2(-Ghat_new) = w / v_final
            wv0 *= rcpf_(v0); wv1 *= rcpf_(v1);
            v0 = wv0; v1 = wv1;
        } else {
            // fgw = sum P * b_final = sum(P*b) - Δt*z - Δr*s   (per column)
            fgw = (gb0 - dt0 * z0 - dr0 * s0)
                + (gb1 - dt1 * z1 - dr1 * s1);
        }
    }

    fgw += __shfl_xor_sync(FULLMASK, fgw, 1);
    fgw += __shfl_xor_sync(FULLMASK, fgw, 2);
    if (cl == 0)
        out[(node_base + nl) * TT + t] = fgw * SCALEBACK;
}

extern "C" void kernel_launch(void* const* d_in, const int* in_sizes, int n_in,
                              void* d_out, int out_size) {
    (void)in_sizes; (void)n_in; (void)out_size;
    const float* x  = (const float*)d_in[0];
    const int*   ei = (const int*)d_in[1];
    const float* tf = (const float*)d_in[2];
    const float* tm = (const float*)d_in[3];
    float* out = (float*)d_out;

    const int smem_bytes = (8192 + 4352 + 1152 + 128 + 68) * 4;  // 55568 B
    cudaFuncSetAttribute(ltfgw_kernel,
                         cudaFuncAttributeMaxDynamicSharedMemorySize, smem_bytes);
    ltfgw_kernel<<<NND / NODES_PER_BLK, THREADS, smem_bytes>>>(
        x, ei + NND * DEG /* dst row */, tf, tm, out);
}

// round 5
// speedup vs baseline: 1.0478x; 1.0478x over previous
#include <cuda_runtime.h>

#define FULLMASK 0xffffffffu
typedef unsigned long long u64;

constexpr int NND = 20000;
constexpr int DEG = 16;
constexpr int NQ  = 17;
constexpr int TT  = 16;
constexpr int MM  = 8;
constexpr int DD  = 64;
constexpr int NODES_PER_BLK = 4;
constexpr int THREADS = 256;

constexpr float SIG       = 14.4269504088896340f;   // log2(e)/EPS
constexpr float LOGP2     = -4.0874628412503390f;   // log2(1/17)
constexpr float LOGQ2     = -3.0f;                  // log2(1/8)
constexpr float SCALEBACK = 0.0693147180559945f;    // EPS*ln(2)

__device__ __forceinline__ float ex2f_(float x){float y;asm("ex2.approx.ftz.f32 %0,%1;":"=f"(y):"f"(x));return y;}
__device__ __forceinline__ float lg2f_(float x){float y;asm("lg2.approx.f32 %0,%1;":"=f"(y):"f"(x));return y;}
__device__ __forceinline__ float rcpf_(float x){float y;asm("rcp.approx.ftz.f32 %0,%1;":"=f"(y):"f"(x));return y;}
__device__ __forceinline__ u64 pk2(float lo,float hi){u64 r;asm("mov.b64 %0,{%1,%2};":"=l"(r):"f"(lo),"f"(hi));return r;}
__device__ __forceinline__ void up2(u64 v,float&lo,float&hi){asm("mov.b64 {%0,%1},%2;":"=f"(lo),"=f"(hi):"l"(v));}
__device__ __forceinline__ u64 fma2(u64 a,u64 b,u64 c){u64 d;asm("fma.rn.f32x2 %0,%1,%2,%3;":"=l"(d):"l"(a),"l"(b),"l"(c));return d;}
__device__ __forceinline__ u64 mul2(u64 a,u64 b){u64 d;asm("mul.rn.f32x2 %0,%1,%2;":"=l"(d):"l"(a),"l"(b));return d;}
__device__ __forceinline__ u64 add2(u64 a,u64 b){u64 d;asm("add.rn.f32x2 %0,%1,%2;":"=l"(d):"l"(a),"l"(b));return d;}

// smem floats: tfT[0,8192) floc[8192,12544) c2s[12544,13696) wcol[13696,13824) rrow[13824,13892)
// transpose buf aliases [0, 8832) (tfT+floc dead by then)
constexpr int SMEMF = 13892;

__global__ __launch_bounds__(THREADS, 2)
void ltfgw_kernel(const float* __restrict__ x,
                  const int*   __restrict__ edge_dst,
                  const float* __restrict__ tf,
                  const float* __restrict__ tm,
                  float*       __restrict__ out)
{
    extern __shared__ float sm[];
    float* tfT  = sm;
    float* floc = sm + 8192;
    float* c2s  = sm + 12544;
    float* wcol = sm + 13696;
    float* rrow = sm + 13824;

    const int tid = threadIdx.x;
    const int node_base = blockIdx.x * NODES_PER_BLK;

    for (int e = tid; e < TT*MM*DD; e += THREADS) {
        int d = e & 63, tj = e >> 6;
        tfT[d*128 + tj] = tf[e];
    }
    for (int e = tid; e < TT*MM*MM; e += THREADS)
        c2s[(e>>3)*9 + (e&7)] = tm[e];

    for (int li = tid; li < NODES_PER_BLK*NQ*(DD/4); li += THREADS) {
        int row = li >> 4, q = li & 15;
        int nl = row / NQ, i = row - nl*NQ;
        int node = node_base + nl;
        int g = (i == 0) ? node : edge_dst[node*DEG + (i-1)];
        reinterpret_cast<float4*>(floc)[row*16 + q] =
            reinterpret_cast<const float4*>(x)[g*16 + q];
    }
    __syncthreads();

    if (tid < 128) {
        float sq = 0.f;
        #pragma unroll 8
        for (int d = 0; d < DD; d++) { float v = tfT[d*128 + tid]; sq += v*v; }
        float bb = 0.f;
        #pragma unroll
        for (int k = 0; k < MM; k++) { float c = c2s[tid*9 + k]; bb += c*c; }
        wcol[tid] = 0.5f*(sq + 0.125f*bb);
    } else if (tid < 128 + NODES_PER_BLK*NQ) {
        int rid = tid - 128;
        float sq = 0.f;
        #pragma unroll 8
        for (int d = 0; d < DD; d++) {
            float v = floc[rid*64 + ((d + rid) & 63)];
            sq += v*v;
        }
        float a = ((rid % NQ) == 0) ? (16.f/17.f) : (1.f/17.f);
        rrow[rid] = 0.5f*(sq + a);
    }
    __syncthreads();

    const int w = tid >> 5, lane = tid & 31;
    const int nl = w >> 1;
    const int grp = lane >> 2, cl = lane & 3;
    const int t = (w & 1)*8 + grp;
    const int j0 = cl*2;
    const int col0 = t*8 + j0;
    const int lb = lane & ~3;

    // ---- feature-cost GEMM (column layout, 2 cols/lane) ----
    float b0[NQ], b1[NQ];
    #pragma unroll
    for (int i = 0; i < NQ; i++) { b0[i] = 0.f; b1[i] = 0.f; }
    const float* fl = floc + nl*NQ*DD;
    #pragma unroll 2
    for (int d4 = 0; d4 < DD; d4 += 4) {
        float2 t0 = *reinterpret_cast<const float2*>(&tfT[(d4+0)*128 + col0]);
        float2 t1 = *reinterpret_cast<const float2*>(&tfT[(d4+1)*128 + col0]);
        float2 t2 = *reinterpret_cast<const float2*>(&tfT[(d4+2)*128 + col0]);
        float2 t3 = *reinterpret_cast<const float2*>(&tfT[(d4+3)*128 + col0]);
        #pragma unroll
        for (int i = 0; i < NQ; i++) {
            float4 f4 = *reinterpret_cast<const float4*>(&fl[i*DD + d4]);
            b0[i] += f4.x*t0.x + f4.y*t1.x + f4.z*t2.x + f4.w*t3.x;
            b1[i] += f4.x*t0.y + f4.y*t1.y + f4.z*t2.y + f4.w*t3.y;
        }
    }
    {
        const float w0c = wcol[col0], w1c = wcol[col0+1];
        #pragma unroll
        for (int i = 0; i < NQ; i++) {
            float r = rrow[nl*NQ + i];
            b0[i] = (r + w0c - b0[i])*SIG;
            b1[i] = (r + w1c - b1[i])*SIG;
        }
    }
    // fold initial H (uniform plan)
    {
        float cs0 = 0.f, cs1 = 0.f;
        const float* c2r0 = &c2s[col0*9];
        const float* c2r1 = &c2s[(col0+1)*9];
        #pragma unroll
        for (int k = 0; k < MM; k++) { cs0 += c2r0[k]; cs1 += c2r1[k]; }
        float ht0 = SIG*(16.f/136.f)*cs0, hr0 = SIG*(1.f/136.f)*cs0;
        float ht1 = SIG*(16.f/136.f)*cs1, hr1 = SIG*(1.f/136.f)*cs1;
        b0[0] -= ht0; b1[0] -= ht1;
        #pragma unroll
        for (int i = 1; i < NQ; i++) { b0[i] -= hr0; b1[i] -= hr1; }
    }
    __syncthreads();   // all warps past GEMM: tfT/floc now dead (buf alias safe)

    // ---- 2 log-domain warmup iterations (column layout) ----
    float F[NQ], G0 = 0.f, G1 = 0.f;
    #pragma unroll 1
    for (int it = 0; it < 2; it++) {
        #pragma unroll
        for (int i = 0; i < NQ; i++) {
            float v0l = G0 - b0[i], v1l = G1 - b1[i];
            float mx = fmaxf(v0l, v1l);
            mx = fmaxf(mx, __shfl_xor_sync(FULLMASK, mx, 1));
            mx = fmaxf(mx, __shfl_xor_sync(FULLMASK, mx, 2));
            float s = ex2f_(v0l - mx) + ex2f_(v1l - mx);
            s += __shfl_xor_sync(FULLMASK, s, 1);
            s += __shfl_xor_sync(FULLMASK, s, 2);
            F[i] = LOGP2 - (lg2f_(s) + mx);
        }
        float m0 = F[0]-b0[0], m1 = F[0]-b1[0];
        #pragma unroll
        for (int i = 1; i < NQ; i++) {
            m0 = fmaxf(m0, F[i]-b0[i]);
            m1 = fmaxf(m1, F[i]-b1[i]);
        }
        float s0l = 0.f, s1l = 0.f;
        #pragma unroll
        for (int i = 0; i < NQ; i++) {
            s0l += ex2f_(F[i]-b0[i]-m0);
            s1l += ex2f_(F[i]-b1[i]-m1);
        }
        G0 = LOGQ2 - (lg2f_(s0l) + m0);
        G1 = LOGQ2 - (lg2f_(s1l) + m1);
    }

    // anchors
    float Fh[5] = {0.f,0.f,0.f,0.f,0.f};
    #pragma unroll
    for (int r = 0; r < NQ; r++)
        if ((r & 3) == cl) Fh[r >> 2] = F[r];
    float Gh[8];
    #pragma unroll
    for (int jj = 0; jj < 4; jj++) {
        Gh[2*jj]   = __shfl_sync(FULLMASK, G0, lb + jj);
        Gh[2*jj+1] = __shfl_sync(FULLMASK, G1, lb + jj);
    }

    // build K (column layout) then transpose through smem to row layout
    float K0[NQ], K1[NQ];
    #pragma unroll
    for (int i = 0; i < NQ; i++) {
        K0[i] = ex2f_(F[i] + G0 - b0[i]);
        K1[i] = ex2f_(F[i] + G1 - b1[i]);
    }
    float* wb = sm + w*1104 + grp*138;
    #pragma unroll
    for (int i = 0; i < NQ; i++)
        *reinterpret_cast<u64*>(wb + i*8 + 2*cl) = pk2(K0[i], K1[i]);
    __syncwarp();
    u64 Kp[5][4];
    #pragma unroll
    for (int s = 0; s < 4; s++)
        #pragma unroll
        for (int jj = 0; jj < 4; jj++)
            Kp[s][jj] = *reinterpret_cast<const u64*>(wb + (cl + 4*s)*8 + 2*jj);
    #pragma unroll
    for (int jj = 0; jj < 4; jj++)
        Kp[4][jj] = (cl == 0) ? *reinterpret_cast<const u64*>(wb + 16*8 + 2*jj)
                              : pk2(0.f, 0.f);

    const float bias4 = (cl == 0) ? 0.f : 1.f;
    u64 v2[4], zold2[4];
    #pragma unroll
    for (int jj = 0; jj < 4; jj++) {
        v2[jj]    = pk2(1.f, 1.f);
        zold2[jj] = pk2(1.f/136.f, 1.f/136.f);
    }

    float ti[5];
    float fgw = 0.f;

    #pragma unroll 1
    for (int outer = 0; outer < 4; outer++) {
        const int nit = outer ? 10 : 8;
        #pragma unroll 1
        for (int it = 0; it < nit; it++) {
            u64 cs2[4];
            #pragma unroll
            for (int jj = 0; jj < 4; jj++) cs2[jj] = pk2(0.f, 0.f);
            #pragma unroll
            for (int s = 0; s < 5; s++) {
                u64 acc = mul2(Kp[s][0], v2[0]);
                acc = fma2(Kp[s][1], v2[1], acc);
                acc = fma2(Kp[s][2], v2[2], acc);
                acc = fma2(Kp[s][3], v2[3], acc);
                float lo, hi; up2(acc, lo, hi);
                float rs = lo + hi + (s == 4 ? bias4 : 0.f);
                float tv = rcpf_(rs);
                ti[s] = tv;
                u64 t2 = pk2(tv, tv);
                cs2[0] = fma2(Kp[s][0], t2, cs2[0]);
                cs2[1] = fma2(Kp[s][1], t2, cs2[1]);
                cs2[2] = fma2(Kp[s][2], t2, cs2[2]);
                cs2[3] = fma2(Kp[s][3], t2, cs2[3]);
            }
            #pragma unroll
            for (int jj = 0; jj < 4; jj++) {
                cs2[jj] = add2(cs2[jj], __shfl_xor_sync(FULLMASK, cs2[jj], 1));
                cs2[jj] = add2(cs2[jj], __shfl_xor_sync(FULLMASK, cs2[jj], 2));
                float lo, hi; up2(cs2[jj], lo, hi);
                v2[jj] = pk2(2.125f*rcpf_(lo), 2.125f*rcpf_(hi));
            }
        }

        // ---- transition: z (row-0 marginals), dr; dt = -dr (since s+z = 1/8) ----
        u64 z2[4];
        {
            float tv = ti[0]*(1.f/17.f);
            u64 t02 = pk2(tv, tv);
            #pragma unroll
            for (int jj = 0; jj < 4; jj++) {
                z2[jj] = mul2(mul2(Kp[0][jj], t02), v2[jj]);    // valid on cl==0
                z2[jj] = __shfl_sync(FULLMASK, z2[jj], lb);     // broadcast
            }
        }
        float dz[8], zz[8];
        #pragma unroll
        for (int jj = 0; jj < 4; jj++) {
            float zl, zh, ol, oh;
            up2(z2[jj], zl, zh); up2(zold2[jj], ol, oh);
            zz[2*jj] = zl; zz[2*jj+1] = zh;
            dz[2*jj] = zl - ol; dz[2*jj+1] = zh - oh;
            zold2[jj] = z2[jj];
        }
        float dr[8];
        #pragma unroll
        for (int j = 0; j < 8; j++) {
            const float* c2r = &c2s[(t*8 + j)*9];
            float a = 0.f;
            #pragma unroll
            for (int k = 0; k < 8; k++) a = fmaf(dz[k], c2r[k], a);
            dr[j] = SIG*a;
        }

        if (outer < 3) {
            u64 m2[4], mt2[4];
            #pragma unroll
            for (int jj = 0; jj < 4; jj++) {
                u64 er = pk2(ex2f_(dr[2*jj]),  ex2f_(dr[2*jj+1]));
                u64 et = pk2(ex2f_(-dr[2*jj]), ex2f_(-dr[2*jj+1]));
                m2[jj]  = mul2(v2[jj], er);
                mt2[jj] = mul2(v2[jj], et);
            }
            #pragma unroll
            for (int s = 0; s < 5; s++) {
                float tv = ti[s]*(1.f/17.f);
                u64 ts2 = pk2(tv, tv);
                #pragma unroll
                for (int jj = 0; jj < 4; jj++) {
                    u64 f = (s == 0 && cl == 0) ? mt2[jj] : m2[jj];
                    Kp[s][jj] = mul2(mul2(Kp[s][jj], ts2), f);
                }
            }
            #pragma unroll
            for (int s = 0; s < 5; s++) Fh[s] += lg2f_(ti[s]) + LOGP2;
            #pragma unroll
            for (int jj = 0; jj < 4; jj++) {
                float vl, vh; up2(v2[jj], vl, vh);
                Gh[2*jj]   += lg2f_(vl);
                Gh[2*jj+1] += lg2f_(vh);
            }
            #pragma unroll
            for (int jj = 0; jj < 4; jj++)
                v2[jj] = pk2(ex2f_(-Gh[2*jj]), ex2f_(-Gh[2*jj+1]));
        } else {
            // ---- epilogue: fgw = sum P*(b - dh);  b = Fh+Gh-lg2(K) ----
            float vv[8];
            #pragma unroll
            for (int jj = 0; jj < 4; jj++) up2(v2[jj], vv[2*jj], vv[2*jj+1]);
            float gb = 0.f;
            #pragma unroll
            for (int s = 0; s < 4; s++) {
                float tv = ti[s]*(1.f/17.f);
                #pragma unroll
                for (int jj = 0; jj < 4; jj++) {
                    float k0, k1; up2(Kp[s][jj], k0, k1);
                    float be0 = Fh[s] + Gh[2*jj]   - lg2f_(fmaxf(k0, 1e-37f));
                    float be1 = Fh[s] + Gh[2*jj+1] - lg2f_(fmaxf(k1, 1e-37f));
                    gb = fmaf(k0*tv*vv[2*jj],   be0, gb);
                    gb = fmaf(k1*tv*vv[2*jj+1], be1, gb);
                }
            }
            if (cl == 0) {
                float tv = ti[4]*(1.f/17.f);
                #pragma unroll
                for (int jj = 0; jj < 4; jj++) {
                    float k0, k1; up2(Kp[4][jj], k0, k1);
                    float be0 = Fh[4] + Gh[2*jj]   - lg2f_(fmaxf(k0, 1e-37f));
                    float be1 = Fh[4] + Gh[2*jj+1] - lg2f_(fmaxf(k1, 1e-37f));
                    gb = fmaf(k0*tv*vv[2*jj],   be0, gb);
                    gb = fmaf(k1*tv*vv[2*jj+1], be1, gb);
                }
            }
            gb += __shfl_xor_sync(FULLMASK, gb, 1);
            gb += __shfl_xor_sync(FULLMASK, gb, 2);
            // corr = sum_j dt*z + dr*s = sum_j dr*(s - z) = sum_j dr*(1/8 - 2z)
            float corr = 0.f;
            #pragma unroll
            for (int j = 0; j < 8; j++)
                corr = fmaf(dr[j], 0.125f - 2.f*zz[j], corr);
            fgw = gb - corr;
        }
    }

    if (cl == 0)
        out[(node_base + nl)*TT + t] = fgw * SCALEBACK;
}

extern "C" void kernel_launch(void* const* d_in, const int* in_sizes, int n_in,
                              void* d_out, int out_size) {
    (void)in_sizes; (void)n_in; (void)out_size;
    const float* x  = (const float*)d_in[0];
    const int*   ei = (const int*)d_in[1];
    const float* tf = (const float*)d_in[2];
    const float* tm = (const float*)d_in[3];
    float* out = (float*)d_out;

    const int smem_bytes = SMEMF * 4;
    cudaFuncSetAttribute(ltfgw_kernel,
                         cudaFuncAttributeMaxDynamicSharedMemorySize, smem_bytes);
    ltfgw_kernel<<<NND / NODES_PER_BLK, THREADS, smem_bytes>>>(
        x, ei + NND * DEG /* dst row */, tf, tm, out);
}

// round 6
// speedup vs baseline: 1.4486x; 1.3826x over previous
#include <cuda_runtime.h>
#define FULLMASK 0xffffffffu
typedef unsigned long long u64;

constexpr int NND=20000, NPB=8, THREADS=256, DEG=16;
constexpr float SIG=14.4269504088896340f;
constexpr float LOGP2=-4.0874628412503390f;
constexpr float LOGQ2=-3.0f;
constexpr float SCALEBACK=0.0693147180559945f;

constexpr int TFT=0;
constexpr int FLOC=10240;
constexpr int C2S=18944;
constexpr int WCOL=20112;
constexpr int RROW=20240;
constexpr int FHS=20376;
constexpr int ZOS=22680;
constexpr int SMEMF=23704;

__device__ __forceinline__ float ex2f_(float x){float y;asm("ex2.approx.ftz.f32 %0,%1;":"=f"(y):"f"(x));return y;}
__device__ __forceinline__ float lg2f_(float x){float y;asm("lg2.approx.f32 %0,%1;":"=f"(y):"f"(x));return y;}
__device__ __forceinline__ float rcpf_(float x){float y;asm("rcp.approx.ftz.f32 %0,%1;":"=f"(y):"f"(x));return y;}
__device__ __forceinline__ u64 pk2(float lo,float hi){u64 r;asm("mov.b64 %0,{%1,%2};":"=l"(r):"f"(lo),"f"(hi));return r;}
__device__ __forceinline__ void up2(u64 v,float&lo,float&hi){asm("mov.b64 {%0,%1},%2;":"=f"(lo),"=f"(hi):"l"(v));}
__device__ __forceinline__ u64 fma2(u64 a,u64 b,u64 c){u64 d;asm("fma.rn.f32x2 %0,%1,%2,%3;":"=l"(d):"l"(a),"l"(b),"l"(c));return d;}
__device__ __forceinline__ u64 mul2(u64 a,u64 b){u64 d;asm("mul.rn.f32x2 %0,%1,%2;":"=l"(d):"l"(a),"l"(b));return d;}
__device__ __forceinline__ u64 add2(u64 a,u64 b){u64 d;asm("add.rn.f32x2 %0,%1,%2;":"=l"(d):"l"(a),"l"(b));return d;}

__global__ __launch_bounds__(THREADS,2)
void ltfgw_kernel(const float* __restrict__ x, const int* __restrict__ ed,
                  const float* __restrict__ tf, const float* __restrict__ tm,
                  float* __restrict__ out)
{
    extern __shared__ float sm[];
    const int tid = threadIdx.x;
    const int nb = blockIdx.x * NPB;

    for (int e = tid; e < 16*8*64; e += THREADS) {
        int d = e & 63, tj = e >> 6;
        sm[TFT + d*160 + (tj>>3)*10 + (tj&7)] = tf[e];
    }
    for (int e = tid; e < 16*64; e += THREADS)
        sm[C2S + (e>>3)*9 + (e&7)] = tm[e];
    for (int li = tid; li < NPB*17*16; li += THREADS) {
        int row = li >> 4, q = li & 15;
        int nl = row / 17, i = row - nl*17, nd = nb + nl;
        int g = (i == 0) ? nd : ed[nd*DEG + i - 1];
        reinterpret_cast<float4*>(sm + FLOC)[row*16 + q] =
            reinterpret_cast<const float4*>(x)[g*16 + q];
    }
    __syncthreads();

    if (tid < 128) {
        float sq = 0.f;
        #pragma unroll 8
        for (int d = 0; d < 64; d++) { float v = sm[TFT + d*160 + (tid>>3)*10 + (tid&7)]; sq += v*v; }
        float bb = 0.f;
        #pragma unroll
        for (int k = 0; k < 8; k++) { float c = sm[C2S + tid*9 + k]; bb += c*c; }
        sm[WCOL + tid] = 0.5f*(sq + 0.125f*bb);
    }
    for (int rid = tid; rid < NPB*17; rid += THREADS) {
        float sq = 0.f;
        #pragma unroll 8
        for (int d = 0; d < 64; d++) { float v = sm[FLOC + rid*64 + ((d+rid)&63)]; sq += v*v; }
        float a = ((rid % 17) == 0) ? (16.f/17.f) : (1.f/17.f);
        sm[RROW + rid] = 0.5f*(sq + a);
    }
    __syncthreads();

    const int w = tid >> 5, lane = tid & 31;
    const int t = lane >> 1, half = lane & 1;
    const int nl = w, cb = t*10;
    int rw[9];
    #pragma unroll
    for (int s = 0; s < 9; s++) rw[s] = (s == 8) ? 16 : half*8 + s;

    u64 b2[9][4];
    #pragma unroll
    for (int s = 0; s < 9; s++)
        #pragma unroll
        for (int jj = 0; jj < 4; jj++) b2[s][jj] = pk2(0.f, 0.f);
    const float* fl = sm + FLOC + nl*1088;
    const float* tft = sm + TFT;
    #pragma unroll 4
    for (int d = 0; d < 64; d += 2) {
        u64 ta[4], tb[4];
        #pragma unroll
        for (int jj = 0; jj < 4; jj++) {
            ta[jj] = *reinterpret_cast<const u64*>(&tft[d*160 + cb + 2*jj]);
            tb[jj] = *reinterpret_cast<const u64*>(&tft[(d+1)*160 + cb + 2*jj]);
        }
        #pragma unroll
        for (int s = 0; s < 9; s++) {
            float2 f2 = *reinterpret_cast<const float2*>(&fl[rw[s]*64 + d]);
            u64 fa = pk2(f2.x, f2.x), fb = pk2(f2.y, f2.y);
            #pragma unroll
            for (int jj = 0; jj < 4; jj++) {
                b2[s][jj] = fma2(fa, ta[jj], b2[s][jj]);
                b2[s][jj] = fma2(fb, tb[jj], b2[s][jj]);
            }
        }
    }
    {
        const u64 nsig = pk2(-SIG, -SIG), negone = pk2(-1.f, -1.f);
        float hr[8];
        #pragma unroll
        for (int c = 0; c < 8; c++) {
            float cs = 0.f;
            #pragma unroll
            for (int k = 0; k < 8; k++) cs += sm[C2S + (t*8+c)*9 + k];
            hr[c] = SIG*cs*(1.f/136.f);
        }
        #pragma unroll
        for (int s = 0; s < 9; s++) {
            float r = sm[RROW + nl*17 + rw[s]];
            float m = (half == 0 && s == 0) ? 16.f : 1.f;
            #pragma unroll
            for (int jj = 0; jj < 4; jj++) {
                float w0 = sm[WCOL + t*8 + 2*jj], w1 = sm[WCOL + t*8 + 2*jj + 1];
                u64 tg = pk2((r+w0)*SIG, (r+w1)*SIG);
                b2[s][jj] = fma2(b2[s][jj], nsig, tg);
                b2[s][jj] = fma2(pk2(m*hr[2*jj], m*hr[2*jj+1]), negone, b2[s][jj]);
            }
        }
    }

    float F[9];
    #pragma unroll
    for (int s = 0; s < 9; s++) {
        float v[8];
        #pragma unroll
        for (int jj = 0; jj < 4; jj++) up2(b2[s][jj], v[2*jj], v[2*jj+1]);
        float mn = v[0];
        #pragma unroll
        for (int c = 1; c < 8; c++) mn = fminf(mn, v[c]);
        float su = 0.f;
        #pragma unroll
        for (int c = 0; c < 8; c++) su += ex2f_(mn - v[c]);
        F[s] = LOGP2 - lg2f_(su) + mn;
    }
    if (half) F[8] = -1e30f;
    float mc[8], sc[8], Gh[8];
    #pragma unroll
    for (int c = 0; c < 8; c++) mc[c] = -1e30f;
    #pragma unroll
    for (int s = 0; s < 9; s++) {
        float v[8];
        #pragma unroll
        for (int jj = 0; jj < 4; jj++) up2(b2[s][jj], v[2*jj], v[2*jj+1]);
        #pragma unroll
        for (int c = 0; c < 8; c++) mc[c] = fmaxf(mc[c], F[s] - v[c]);
    }
    #pragma unroll
    for (int c = 0; c < 8; c++) {
        mc[c] = fmaxf(mc[c], __shfl_xor_sync(FULLMASK, mc[c], 1));
        sc[c] = 0.f;
    }
    #pragma unroll
    for (int s = 0; s < 9; s++) {
        float v[8];
        #pragma unroll
        for (int jj = 0; jj < 4; jj++) up2(b2[s][jj], v[2*jj], v[2*jj+1]);
        #pragma unroll
        for (int c = 0; c < 8; c++) sc[c] += ex2f_(F[s] - v[c] - mc[c]);
    }
    #pragma unroll
    for (int c = 0; c < 8; c++) {
        sc[c] += __shfl_xor_sync(FULLMASK, sc[c], 1);
        Gh[c] = LOGQ2 - lg2f_(sc[c]) - mc[c];
    }

    u64 K2[9][4];
    #pragma unroll
    for (int s = 0; s < 9; s++)
        #pragma unroll
        for (int jj = 0; jj < 4; jj++) {
            float blo, bhi; up2(b2[s][jj], blo, bhi);
            K2[s][jj] = pk2(ex2f_(F[s] + Gh[2*jj] - blo),
                            ex2f_(F[s] + Gh[2*jj+1] - bhi));
        }
    float* fh = sm + FHS + tid*9;
    #pragma unroll
    for (int s = 0; s < 9; s++) fh[s] = F[s];
    float* zo = sm + ZOS + (w*16 + t)*8;
    if (half == 0) {
        #pragma unroll
        for (int c = 0; c < 8; c++) zo[c] = 1.f/136.f;
    }

    u64 v2[4];
    #pragma unroll
    for (int jj = 0; jj < 4; jj++) v2[jj] = pk2(1.f, 1.f);
    float ti[9];
    const float b8 = half ? 1.f : 0.f;
    float fgw = 0.f;

    #pragma unroll 1
    for (int outer = 0; outer < 4; outer++) {
        const int nit = outer ? 10 : 9;
        #pragma unroll 1
        for (int it = 0; it < nit; it++) {
            u64 cs2[4];
            #pragma unroll
            for (int jj = 0; jj < 4; jj++) cs2[jj] = pk2(0.f, 0.f);
            #pragma unroll
            for (int s = 0; s < 9; s++) {
                u64 a = mul2(K2[s][0], v2[0]);
                a = fma2(K2[s][1], v2[1], a);
                a = fma2(K2[s][2], v2[2], a);
                a = fma2(K2[s][3], v2[3], a);
                float lo, hi; up2(a, lo, hi);
                float rs = lo + hi + ((s == 8) ? b8 : 0.f);
                float tv = rcpf_(rs);
                ti[s] = tv;
                u64 t2 = pk2(tv, tv);
                cs2[0] = fma2(K2[s][0], t2, cs2[0]);
                cs2[1] = fma2(K2[s][1], t2, cs2[1]);
                cs2[2] = fma2(K2[s][2], t2, cs2[2]);
                cs2[3] = fma2(K2[s][3], t2, cs2[3]);
            }
            #pragma unroll
            for (int jj = 0; jj < 4; jj++) {
                cs2[jj] = add2(cs2[jj], __shfl_xor_sync(FULLMASK, cs2[jj], 1));
                float lo, hi; up2(cs2[jj], lo, hi);
                v2[jj] = pk2(2.125f*rcpf_(lo), 2.125f*rcpf_(hi));
            }
        }

        float tv0 = ti[0]*(1.f/17.f);
        u64 t02 = pk2(tv0, tv0);
        u64 z2[4];
        #pragma unroll
        for (int jj = 0; jj < 4; jj++) {
            z2[jj] = mul2(mul2(K2[0][jj], t02), v2[jj]);
            z2[jj] = __shfl_sync(FULLMASK, z2[jj], lane & ~1);
        }
        float zz[8], dz[8];
        #pragma unroll
        for (int jj = 0; jj < 4; jj++) up2(z2[jj], zz[2*jj], zz[2*jj+1]);
        #pragma unroll
        for (int c = 0; c < 8; c++) dz[c] = zz[c] - zo[c];
        if (half == 0) {
            #pragma unroll
            for (int c = 0; c < 8; c++) zo[c] = zz[c];
        }
        float dr[8];
        #pragma unroll
        for (int j = 0; j < 8; j++) {
            float a = 0.f;
            #pragma unroll
            for (int k = 0; k < 8; k++) a = fmaf(dz[k], sm[C2S + (t*8+j)*9 + k], a);
            dr[j] = SIG*a;
        }

        if (outer < 3) {
            u64 m2[4], mt2[4];
            #pragma unroll
            for (int jj = 0; jj < 4; jj++) {
                m2[jj]  = mul2(v2[jj], pk2(ex2f_(dr[2*jj]),  ex2f_(dr[2*jj+1])));
                mt2[jj] = mul2(v2[jj], pk2(ex2f_(-dr[2*jj]), ex2f_(-dr[2*jj+1])));
            }
            #pragma unroll
            for (int s = 0; s < 9; s++) {
                float tsv = ti[s]*(1.f/17.f);
                u64 ts2 = pk2(tsv, tsv);
                #pragma unroll
                for (int jj = 0; jj < 4; jj++) {
                    u64 f2 = (half == 0 && s == 0) ? mt2[jj] : m2[jj];
                    K2[s][jj] = mul2(mul2(K2[s][jj], ts2), f2);
                }
            }
            #pragma unroll
            for (int s = 0; s < 9; s++) fh[s] += lg2f_(ti[s]) + LOGP2;
            float vv[8];
            #pragma unroll
            for (int jj = 0; jj < 4; jj++) up2(v2[jj], vv[2*jj], vv[2*jj+1]);
            #pragma unroll
            for (int c = 0; c < 8; c++) Gh[c] += lg2f_(vv[c]);
            #pragma unroll
            for (int jj = 0; jj < 4; jj++)
                v2[jj] = pk2(ex2f_(-Gh[2*jj]), ex2f_(-Gh[2*jj+1]));
        } else {
            float vv[8];
            #pragma unroll
            for (int jj = 0; jj < 4; jj++) up2(v2[jj], vv[2*jj], vv[2*jj+1]);
            float gb = 0.f;
            #pragma unroll
            for (int s = 0; s < 9; s++) {
                float tsv = ti[s]*(1.f/17.f);
                float fhs = fh[s];
                #pragma unroll
                for (int jj = 0; jj < 4; jj++) {
                    float k0, k1; up2(K2[s][jj], k0, k1);
                    gb = fmaf(k0*tsv*vv[2*jj],
                              fhs + Gh[2*jj]   - lg2f_(fmaxf(k0, 1e-37f)), gb);
                    gb = fmaf(k1*tsv*vv[2*jj+1],
                              fhs + Gh[2*jj+1] - lg2f_(fmaxf(k1, 1e-37f)), gb);
                }
            }
            gb += __shfl_xor_sync(FULLMASK, gb, 1);
            float corr = 0.f;
            #pragma unroll
            for (int j = 0; j < 8; j++) corr = fmaf(dr[j], 0.125f - 2.f*zz[j], corr);
            fgw = gb - corr;
        }
    }

    if (half == 0)
        out[(nb + w)*16 + t] = fgw * SCALEBACK;
}

extern "C" void kernel_launch(void* const* d_in, const int* in_sizes, int n_in,
                              void* d_out, int out_size) {
    (void)in_sizes; (void)n_in; (void)out_size;
    const float* x  = (const float*)d_in[0];
    const int*   ei = (const int*)d_in[1];
    const float* tf = (const float*)d_in[2];
    const float* tm = (const float*)d_in[3];
    float* out = (float*)d_out;

    const int smem_bytes = SMEMF * 4;
    cudaFuncSetAttribute(ltfgw_kernel,
                         cudaFuncAttributeMaxDynamicSharedMemorySize, smem_bytes);
    ltfgw_kernel<<<NND / NPB, THREADS, smem_bytes>>>(
        x, ei + NND * DEG, tf, tm, out);
}